// round 8
// baseline (speedup 1.0000x reference)
#include <cuda_runtime.h>
#include <cstdint>

// ============================================================================
// LoRA layer as one tf32 GEMM on the mma.sync (HMMA) path (ptxas targets
// sm_103 plain — no tcgen05 available).
//   out[8192,2048] = x[8192,2048] @ (W + A@B)[2048,2048]
//   1) convert_x:   x fp32 -> tf32(RNA) bits               (g_x, [M,K])
//   2) build_weffT: (W + A@B)^T -> tf32(RNA) bits          (g_WT, [N,K])
//   3) gemm: 128x256 CTA tile, BK=32, 256 thr (8 warps, 64x64 warp tile),
//      4-stage cp.async, ldmatrix.x4 + mma.sync.m16n8k8.tf32
// Round-8 change: warp tile 64x32 -> 64x64. Cuts smem/ldmatrix traffic per
// FLOP by 1.5x and ldsm instruction count by 2x (the measured bottleneck).
// ============================================================================

#define M_DIM 8192
#define N_DIM 2048
#define K_DIM 2048

#define BM 128
#define BN 256
#define BK 32                      // tf32 elems (128 bytes) per row per stage
#define STAGES 4
#define KITERS (K_DIM / BK)        // 64

#define A_STAGE_BYTES (BM * 128)   // 16 KB
#define B_STAGE_BYTES (BN * 128)   // 32 KB
#define STAGE_BYTES (A_STAGE_BYTES + B_STAGE_BYTES)   // 48 KB
#define SMEM_TOTAL (STAGES * STAGE_BYTES)             // 192 KB

__device__ uint32_t g_x[(size_t)M_DIM * K_DIM];    // x as tf32 bits, [M,K]
__device__ uint32_t g_WT[(size_t)N_DIM * K_DIM];   // (W+AB)^T tf32 bits, [N,K]

// ---------------------------------------------------------------------------
// helpers
// ---------------------------------------------------------------------------
__device__ __forceinline__ uint32_t smem_u32(const void* p) {
    uint32_t a;
    asm("{ .reg .u64 t; cvta.to.shared.u64 t, %1; cvt.u32.u64 %0, t; }"
        : "=r"(a) : "l"(p));
    return a;
}
__device__ __forceinline__ uint32_t f2tf32(float f) {
    uint32_t r;
    asm("cvt.rna.tf32.f32 %0, %1;" : "=r"(r) : "f"(f));
    return r;
}
__device__ __forceinline__ void cp_async16(uint32_t s, const void* g) {
    asm volatile("cp.async.cg.shared.global [%0], [%1], 16;"
                 :: "r"(s), "l"(g) : "memory");
}
__device__ __forceinline__ void cp_commit() {
    asm volatile("cp.async.commit_group;" ::: "memory");
}
template <int N> __device__ __forceinline__ void cp_wait() {
    asm volatile("cp.async.wait_group %0;" :: "n"(N) : "memory");
}
__device__ __forceinline__ void ldsm_x4(uint32_t* r, uint32_t addr) {
    asm volatile("ldmatrix.sync.aligned.m8n8.x4.shared.b16 {%0,%1,%2,%3}, [%4];"
                 : "=r"(r[0]), "=r"(r[1]), "=r"(r[2]), "=r"(r[3]) : "r"(addr));
}
__device__ __forceinline__ void mma_tf32(float* c, const uint32_t* a, const uint32_t* b) {
    asm volatile(
        "mma.sync.aligned.m16n8k8.row.col.f32.tf32.tf32.f32 "
        "{%0,%1,%2,%3}, {%4,%5,%6,%7}, {%8,%9}, {%0,%1,%2,%3};"
        : "+f"(c[0]), "+f"(c[1]), "+f"(c[2]), "+f"(c[3])
        : "r"(a[0]), "r"(a[1]), "r"(a[2]), "r"(a[3]), "r"(b[0]), "r"(b[1]));
}

// ---------------------------------------------------------------------------
// Kernel 1: x fp32 -> tf32(RNA) bits
// ---------------------------------------------------------------------------
__global__ void convert_x_kernel(const float4* __restrict__ x, uint4* __restrict__ gx) {
    int idx = blockIdx.x * blockDim.x + threadIdx.x;
    float4 v = x[idx];
    uint4 o;
    o.x = f2tf32(v.x); o.y = f2tf32(v.y); o.z = f2tf32(v.z); o.w = f2tf32(v.w);
    gx[idx] = o;
}

// ---------------------------------------------------------------------------
// Kernel 2: W_eff^T: out[n*K + c] = tf32( W[c*N + n] + sum_r A[c,r]*B[r,n] )
// ---------------------------------------------------------------------------
__global__ void build_weffT_kernel(const float* __restrict__ W,
                                   const float* __restrict__ A,
                                   const float* __restrict__ Bk,
                                   uint32_t* __restrict__ out) {
    __shared__ float t[32][33];
    int ci = blockIdx.y * 32;
    int ni = blockIdx.x * 32;
    #pragma unroll
    for (int i = 0; i < 4; i++) {
        int c = ci + threadIdx.y + i * 8;
        int n = ni + threadIdx.x;
        float w = W[(size_t)c * N_DIM + n];
        float a0 = A[c * 4 + 0], a1 = A[c * 4 + 1], a2 = A[c * 4 + 2], a3 = A[c * 4 + 3];
        w += a0 * Bk[n] + a1 * Bk[N_DIM + n] + a2 * Bk[2 * N_DIM + n] + a3 * Bk[3 * N_DIM + n];
        t[threadIdx.y + i * 8][threadIdx.x] = w;
    }
    __syncthreads();
    #pragma unroll
    for (int i = 0; i < 4; i++) {
        int n = ni + threadIdx.y + i * 8;
        int c = ci + threadIdx.x;
        out[(size_t)n * K_DIM + c] = f2tf32(t[threadIdx.x][threadIdx.y + i * 8]);
    }
}

// ---------------------------------------------------------------------------
// Kernel 3: tf32 mma.sync GEMM, 128x256 per CTA, 256 threads
//   warp grid 2(M) x 4(N); warp tile 64x64: 4 m-tiles(16) x 8 n-tiles(8)
// smem row = 32 tf32 = 128B = 8 chunks of 16B, chunk swizzle c ^= (row & 7)
// ---------------------------------------------------------------------------
__global__ __launch_bounds__(256, 1)
void gemm_tf32_mma(const uint32_t* __restrict__ gA,   // [M,K]
                   const uint32_t* __restrict__ gB,   // [N,K]
                   float* __restrict__ C) {
    extern __shared__ char smem[];
    const uint32_t sbase = smem_u32(smem);

    const int tid  = threadIdx.x;
    const int wid  = tid >> 5;
    const int lane = tid & 31;
    const int wm = wid & 1;        // 0..1  (M)
    const int wn = wid >> 1;       // 0..3  (N)

    const int bm = blockIdx.y;     // 0..63
    const int bn = blockIdx.x;     // 0..7

    // ---- cp.async mappings --------------------------------------------------
    // A: 128 rows x 8 chunks = 1024 chunks -> 4 per thread (2 threads/row)
    const int arow = tid >> 1;                 // 0..127
    const int ac0  = (tid & 1) * 4;            // chunks ac0..ac0+3
    // B: 256 rows x 8 chunks -> one full 128B row per thread
    const int brow = tid;                      // 0..255

    const uint32_t* gAp = gA + (size_t)(bm * BM + arow) * K_DIM;
    const uint32_t* gBp = gB + (size_t)(bn * BN + brow) * K_DIM;

    auto load_stage = [&](int s) {
        uint32_t st = sbase + (s % STAGES) * STAGE_BYTES;
        uint32_t sa = st + arow * 128;
        uint32_t sb = st + A_STAGE_BYTES + brow * 128;
        const uint32_t* ga = gAp + s * BK;
        const uint32_t* gb = gBp + s * BK;
        #pragma unroll
        for (int j = 0; j < 4; j++) {
            int c = ac0 + j;
            cp_async16(sa + ((c ^ (arow & 7)) << 4), ga + c * 4);
        }
        #pragma unroll
        for (int j = 0; j < 8; j++) {
            cp_async16(sb + ((j ^ (brow & 7)) << 4), gb + j * 4);
        }
    };

    // ---- ldmatrix address bases --------------------------------------------
    // A (m16k8, ldsm_x4): row = wm*64 + mt*16 + (lane&15); k-half = lane>>4
    // B (two n8k8 tiles per ldsm_x4):
    //   row = wn*64 + ntp*16 + ((lane>>4)<<3) + (lane&7); k-half = (lane>>3)&1
    //   -> regs {r0,r1} = n-tile 2*ntp, {r2,r3} = n-tile 2*ntp+1
    const int a_r = wm * 64 + (lane & 15);
    const int a_h = lane >> 4;                     // 0/1
    const int b_r = wn * 64 + ((lane >> 4) << 3) + (lane & 7);
    const int b_h = (lane >> 3) & 1;
    const int r7  = lane & 7;                      // == row&7 for all frag rows

    float acc[4][8][4];
    #pragma unroll
    for (int i = 0; i < 4; i++)
        #pragma unroll
        for (int j = 0; j < 8; j++)
            #pragma unroll
            for (int q = 0; q < 4; q++)
                acc[i][j][q] = 0.0f;

    // ---- prologue ----------------------------------------------------------
    #pragma unroll
    for (int s = 0; s < STAGES - 1; s++) { load_stage(s); cp_commit(); }

    // ---- main loop ---------------------------------------------------------
    for (int k = 0; k < KITERS; k++) {
        cp_wait<STAGES - 2>();
        __syncthreads();

        uint32_t st = sbase + (k % STAGES) * STAGE_BYTES;
        uint32_t sa = st + a_r * 128;
        uint32_t sb = st + A_STAGE_BYTES + b_r * 128;

        #pragma unroll
        for (int ks = 0; ks < 4; ks++) {
            uint32_t afr[4][4];
            uint32_t bfr[4][4];
            const int ca = ((2 * ks + a_h) ^ r7) << 4;
            const int cb = ((2 * ks + b_h) ^ r7) << 4;
            #pragma unroll
            for (int mt = 0; mt < 4; mt++)
                ldsm_x4(afr[mt], sa + mt * (16 * 128) + ca);
            #pragma unroll
            for (int ntp = 0; ntp < 4; ntp++)
                ldsm_x4(bfr[ntp], sb + ntp * (16 * 128) + cb);
            #pragma unroll
            for (int mt = 0; mt < 4; mt++)
                #pragma unroll
                for (int ntp = 0; ntp < 4; ntp++) {
                    mma_tf32(acc[mt][2 * ntp + 0], afr[mt], &bfr[ntp][0]);
                    mma_tf32(acc[mt][2 * ntp + 1], afr[mt], &bfr[ntp][2]);
                }
        }

        if (k + STAGES - 1 < KITERS) load_stage(k + STAGES - 1);
        cp_commit();
    }

    // ---- epilogue ----------------------------------------------------------
    const int er = lane >> 2;
    const int ec = (lane & 3) * 2;
    #pragma unroll
    for (int mt = 0; mt < 4; mt++) {
        int m0 = bm * BM + wm * 64 + mt * 16 + er;
        #pragma unroll
        for (int nt = 0; nt < 8; nt++) {
            int n0 = bn * BN + wn * 64 + nt * 8 + ec;
            *(float2*)(C + (size_t)m0 * N_DIM + n0) =
                make_float2(acc[mt][nt][0], acc[mt][nt][1]);
            *(float2*)(C + (size_t)(m0 + 8) * N_DIM + n0) =
                make_float2(acc[mt][nt][2], acc[mt][nt][3]);
        }
    }
}

// ---------------------------------------------------------------------------
// Launch
// ---------------------------------------------------------------------------
extern "C" void kernel_launch(void* const* d_in, const int* in_sizes, int n_in,
                              void* d_out, int out_size) {
    const float* x  = (const float*)d_in[0];   // [8192, 2048]
    const float* W  = (const float*)d_in[1];   // [2048, 2048]
    const float* A  = (const float*)d_in[2];   // [2048, 4]
    const float* Bk = (const float*)d_in[3];   // [4, 2048]
    float* out = (float*)d_out;

    uint32_t *gx, *gwt;
    cudaGetSymbolAddress((void**)&gx, g_x);
    cudaGetSymbolAddress((void**)&gwt, g_WT);

    // 1) x -> tf32 bits
    {
        int total4 = (M_DIM * K_DIM) / 4;
        convert_x_kernel<<<total4 / 256, 256>>>((const float4*)x, (uint4*)gx);
    }
    // 2) W_eff^T -> tf32 bits
    {
        dim3 grid(N_DIM / 32, K_DIM / 32);
        dim3 block(32, 8);
        build_weffT_kernel<<<grid, block>>>(W, A, Bk, gwt);
    }
    // 3) GEMM
    {
        static bool attr_set = false;
        if (!attr_set) {
            cudaFuncSetAttribute(gemm_tf32_mma,
                                 cudaFuncAttributeMaxDynamicSharedMemorySize, SMEM_TOTAL);
            attr_set = true;
        }
        dim3 grid(N_DIM / BN, M_DIM / BM);   // (8, 64)
        gemm_tf32_mma<<<grid, 256, SMEM_TOTAL>>>(gx, gwt, out);
    }
}

// round 9
// speedup vs baseline: 1.2519x; 1.2519x over previous
#include <cuda_runtime.h>
#include <cstdint>

// ============================================================================
// LoRA layer as one tf32 GEMM on the mma.sync (HMMA) path (ptxas targets
// sm_103 plain — no tcgen05 available).
//   out[8192,2048] = x[8192,2048] @ (W + A@B)[2048,2048]
//   1) convert_x:   x fp32 -> tf32(RNA) bits               (g_x, [M,K])
//   2) build_weffT: (W + A@B)^T -> tf32(RNA) bits          (g_WT, [N,K])
//   3) gemm: 128x256 CTA tile, BK=32, 512 thr (16 warps, 64x32 warp tile),
//      4-stage cp.async, ldmatrix + mma.sync.m16n8k8.tf32
// Round-9 changes vs best (R7):
//   - fragment double-buffering: ldsm for ks+1 issued before mma of ks, so
//     the smem crossbar and the HMMA pipe overlap instead of phase-locking
//   - B fragments via paired ldsm_x4 (2 n-tiles per instr; mapping validated
//     in round 8), ldsm count 32 -> 24 per warp per k-iter
//   - next-stage cp.async issued right after the barrier, not after the MMAs
// ============================================================================

#define M_DIM 8192
#define N_DIM 2048
#define K_DIM 2048

#define BM 128
#define BN 256
#define BK 32                      // tf32 elems (128 bytes) per row per stage
#define STAGES 4
#define KITERS (K_DIM / BK)        // 64

#define A_STAGE_BYTES (BM * 128)   // 16 KB
#define B_STAGE_BYTES (BN * 128)   // 32 KB
#define STAGE_BYTES (A_STAGE_BYTES + B_STAGE_BYTES)   // 48 KB
#define SMEM_TOTAL (STAGES * STAGE_BYTES)             // 192 KB

__device__ uint32_t g_x[(size_t)M_DIM * K_DIM];    // x as tf32 bits, [M,K]
__device__ uint32_t g_WT[(size_t)N_DIM * K_DIM];   // (W+AB)^T tf32 bits, [N,K]

// ---------------------------------------------------------------------------
// helpers
// ---------------------------------------------------------------------------
__device__ __forceinline__ uint32_t smem_u32(const void* p) {
    uint32_t a;
    asm("{ .reg .u64 t; cvta.to.shared.u64 t, %1; cvt.u32.u64 %0, t; }"
        : "=r"(a) : "l"(p));
    return a;
}
__device__ __forceinline__ uint32_t f2tf32(float f) {
    uint32_t r;
    asm("cvt.rna.tf32.f32 %0, %1;" : "=r"(r) : "f"(f));
    return r;
}
__device__ __forceinline__ void cp_async16(uint32_t s, const void* g) {
    asm volatile("cp.async.cg.shared.global [%0], [%1], 16;"
                 :: "r"(s), "l"(g) : "memory");
}
__device__ __forceinline__ void cp_commit() {
    asm volatile("cp.async.commit_group;" ::: "memory");
}
template <int N> __device__ __forceinline__ void cp_wait() {
    asm volatile("cp.async.wait_group %0;" :: "n"(N) : "memory");
}
__device__ __forceinline__ void ldsm_x4(uint32_t* r, uint32_t addr) {
    asm volatile("ldmatrix.sync.aligned.m8n8.x4.shared.b16 {%0,%1,%2,%3}, [%4];"
                 : "=r"(r[0]), "=r"(r[1]), "=r"(r[2]), "=r"(r[3]) : "r"(addr));
}
__device__ __forceinline__ void mma_tf32(float* c, const uint32_t* a, const uint32_t* b) {
    asm volatile(
        "mma.sync.aligned.m16n8k8.row.col.f32.tf32.tf32.f32 "
        "{%0,%1,%2,%3}, {%4,%5,%6,%7}, {%8,%9}, {%0,%1,%2,%3};"
        : "+f"(c[0]), "+f"(c[1]), "+f"(c[2]), "+f"(c[3])
        : "r"(a[0]), "r"(a[1]), "r"(a[2]), "r"(a[3]), "r"(b[0]), "r"(b[1]));
}

// ---------------------------------------------------------------------------
// Kernel 1: x fp32 -> tf32(RNA) bits
// ---------------------------------------------------------------------------
__global__ void convert_x_kernel(const float4* __restrict__ x, uint4* __restrict__ gx) {
    int idx = blockIdx.x * blockDim.x + threadIdx.x;
    float4 v = x[idx];
    uint4 o;
    o.x = f2tf32(v.x); o.y = f2tf32(v.y); o.z = f2tf32(v.z); o.w = f2tf32(v.w);
    gx[idx] = o;
}

// ---------------------------------------------------------------------------
// Kernel 2: W_eff^T: out[n*K + c] = tf32( W[c*N + n] + sum_r A[c,r]*B[r,n] )
// ---------------------------------------------------------------------------
__global__ void build_weffT_kernel(const float* __restrict__ W,
                                   const float* __restrict__ A,
                                   const float* __restrict__ Bk,
                                   uint32_t* __restrict__ out) {
    __shared__ float t[32][33];
    int ci = blockIdx.y * 32;
    int ni = blockIdx.x * 32;
    #pragma unroll
    for (int i = 0; i < 4; i++) {
        int c = ci + threadIdx.y + i * 8;
        int n = ni + threadIdx.x;
        float w = W[(size_t)c * N_DIM + n];
        float a0 = A[c * 4 + 0], a1 = A[c * 4 + 1], a2 = A[c * 4 + 2], a3 = A[c * 4 + 3];
        w += a0 * Bk[n] + a1 * Bk[N_DIM + n] + a2 * Bk[2 * N_DIM + n] + a3 * Bk[3 * N_DIM + n];
        t[threadIdx.y + i * 8][threadIdx.x] = w;
    }
    __syncthreads();
    #pragma unroll
    for (int i = 0; i < 4; i++) {
        int n = ni + threadIdx.y + i * 8;
        int c = ci + threadIdx.x;
        out[(size_t)n * K_DIM + c] = f2tf32(t[threadIdx.x][threadIdx.y + i * 8]);
    }
}

// ---------------------------------------------------------------------------
// Kernel 3: tf32 mma.sync GEMM, 128x256 per CTA, 512 threads
//   warp grid 2(M) x 8(N); warp tile 64x32: 4 m-tiles(16) x 4 n-tiles(8)
// smem row = 32 tf32 = 128B = 8 chunks of 16B, chunk swizzle c ^= (row & 7)
// ---------------------------------------------------------------------------
__global__ __launch_bounds__(512, 1)
void gemm_tf32_mma(const uint32_t* __restrict__ gA,   // [M,K]
                   const uint32_t* __restrict__ gB,   // [N,K]
                   float* __restrict__ C) {
    extern __shared__ char smem[];
    const uint32_t sbase = smem_u32(smem);

    const int tid  = threadIdx.x;
    const int wid  = tid >> 5;
    const int lane = tid & 31;
    const int wm = wid & 1;        // 0..1  (M)
    const int wn = wid >> 1;       // 0..7  (N)

    const int bm = blockIdx.y;     // 0..63
    const int bn = blockIdx.x;     // 0..7

    // ---- cp.async mappings --------------------------------------------------
    // A: 128 rows x 8 chunks = 1024 chunks -> 2 per thread
    const int arow = tid >> 2;                 // 0..127
    const int ac0  = (tid & 3) * 2;            // chunks ac0, ac0+1
    // B: 256 rows x 8 chunks = 2048 chunks -> 4 per thread
    const int brow = tid >> 1;                 // 0..255
    const int bc0  = (tid & 1) * 4;            // chunks bc0..bc0+3

    const uint32_t* gAp = gA + (size_t)(bm * BM + arow) * K_DIM;
    const uint32_t* gBp = gB + (size_t)(bn * BN + brow) * K_DIM;

    auto load_stage = [&](int s) {
        uint32_t st = sbase + (s % STAGES) * STAGE_BYTES;
        uint32_t sa = st + arow * 128;
        uint32_t sb = st + A_STAGE_BYTES + brow * 128;
        const uint32_t* ga = gAp + s * BK;
        const uint32_t* gb = gBp + s * BK;
        #pragma unroll
        for (int j = 0; j < 2; j++) {
            int c = ac0 + j;
            cp_async16(sa + ((c ^ (arow & 7)) << 4), ga + c * 4);
        }
        #pragma unroll
        for (int j = 0; j < 4; j++) {
            int c = bc0 + j;
            cp_async16(sb + ((c ^ (brow & 7)) << 4), gb + c * 4);
        }
    };

    // ---- ldmatrix address bases --------------------------------------------
    // A (m16k8, ldsm_x4): row = wm*64 + mt*16 + (lane&15); k-half = lane>>4
    // B (two n8k8 tiles per ldsm_x4, mapping validated in R8):
    //   row = wn*32 + ntp*16 + ((lane>>4)<<3) + (lane&7); k-half = (lane>>3)&1
    //   regs {r0,r1} = n-tile 2*ntp, {r2,r3} = n-tile 2*ntp+1
    const int a_r = wm * 64 + (lane & 15);
    const int a_h = lane >> 4;                     // 0/1
    const int b_r = wn * 32 + ((lane >> 4) << 3) + (lane & 7);
    const int b_h = (lane >> 3) & 1;
    const int r7  = lane & 7;

    float acc[4][4][4];
    #pragma unroll
    for (int i = 0; i < 4; i++)
        #pragma unroll
        for (int j = 0; j < 4; j++)
            #pragma unroll
            for (int q = 0; q < 4; q++)
                acc[i][j][q] = 0.0f;

    // ---- prologue ----------------------------------------------------------
    #pragma unroll
    for (int s = 0; s < STAGES - 1; s++) { load_stage(s); cp_commit(); }

    // double-buffered fragments
    uint32_t afr[2][4][4];
    uint32_t bfr[2][2][4];

    // ---- main loop ---------------------------------------------------------
    for (int k = 0; k < KITERS; k++) {
        cp_wait<STAGES - 2>();
        __syncthreads();

        uint32_t st = sbase + (k % STAGES) * STAGE_BYTES;
        uint32_t sa = st + a_r * 128;
        uint32_t sb = st + A_STAGE_BYTES + b_r * 128;

        // prefetch fragments for ks = 0 into buffer 0
        {
            const int ca = ((a_h) ^ r7) << 4;            // 2*0 + a_h
            const int cb = ((b_h) ^ r7) << 4;
            #pragma unroll
            for (int mt = 0; mt < 4; mt++)
                ldsm_x4(afr[0][mt], sa + mt * (16 * 128) + ca);
            #pragma unroll
            for (int ntp = 0; ntp < 2; ntp++)
                ldsm_x4(bfr[0][ntp], sb + ntp * (16 * 128) + cb);
        }

        // issue next-stage global->shared copies early (overlaps with MMAs)
        if (k + STAGES - 1 < KITERS) load_stage(k + STAGES - 1);
        cp_commit();

        #pragma unroll
        for (int ks = 0; ks < 4; ks++) {
            const int cur = ks & 1;
            const int nxt = cur ^ 1;
            if (ks < 3) {
                const int ca = ((2 * (ks + 1) + a_h) ^ r7) << 4;
                const int cb = ((2 * (ks + 1) + b_h) ^ r7) << 4;
                #pragma unroll
                for (int mt = 0; mt < 4; mt++)
                    ldsm_x4(afr[nxt][mt], sa + mt * (16 * 128) + ca);
                #pragma unroll
                for (int ntp = 0; ntp < 2; ntp++)
                    ldsm_x4(bfr[nxt][ntp], sb + ntp * (16 * 128) + cb);
            }
            #pragma unroll
            for (int mt = 0; mt < 4; mt++)
                #pragma unroll
                for (int ntp = 0; ntp < 2; ntp++) {
                    mma_tf32(acc[mt][2 * ntp + 0], afr[cur][mt], &bfr[cur][ntp][0]);
                    mma_tf32(acc[mt][2 * ntp + 1], afr[cur][mt], &bfr[cur][ntp][2]);
                }
        }
    }

    // ---- epilogue ----------------------------------------------------------
    const int er = lane >> 2;
    const int ec = (lane & 3) * 2;
    #pragma unroll
    for (int mt = 0; mt < 4; mt++) {
        int m0 = bm * BM + wm * 64 + mt * 16 + er;
        #pragma unroll
        for (int nt = 0; nt < 4; nt++) {
            int n0 = bn * BN + wn * 32 + nt * 8 + ec;
            *(float2*)(C + (size_t)m0 * N_DIM + n0) =
                make_float2(acc[mt][nt][0], acc[mt][nt][1]);
            *(float2*)(C + (size_t)(m0 + 8) * N_DIM + n0) =
                make_float2(acc[mt][nt][2], acc[mt][nt][3]);
        }
    }
}

// ---------------------------------------------------------------------------
// Launch
// ---------------------------------------------------------------------------
extern "C" void kernel_launch(void* const* d_in, const int* in_sizes, int n_in,
                              void* d_out, int out_size) {
    const float* x  = (const float*)d_in[0];   // [8192, 2048]
    const float* W  = (const float*)d_in[1];   // [2048, 2048]
    const float* A  = (const float*)d_in[2];   // [2048, 4]
    const float* Bk = (const float*)d_in[3];   // [4, 2048]
    float* out = (float*)d_out;

    uint32_t *gx, *gwt;
    cudaGetSymbolAddress((void**)&gx, g_x);
    cudaGetSymbolAddress((void**)&gwt, g_WT);

    // 1) x -> tf32 bits
    {
        int total4 = (M_DIM * K_DIM) / 4;
        convert_x_kernel<<<total4 / 256, 256>>>((const float4*)x, (uint4*)gx);
    }
    // 2) W_eff^T -> tf32 bits
    {
        dim3 grid(N_DIM / 32, K_DIM / 32);
        dim3 block(32, 8);
        build_weffT_kernel<<<grid, block>>>(W, A, Bk, gwt);
    }
    // 3) GEMM
    {
        static bool attr_set = false;
        if (!attr_set) {
            cudaFuncSetAttribute(gemm_tf32_mma,
                                 cudaFuncAttributeMaxDynamicSharedMemorySize, SMEM_TOTAL);
            attr_set = true;
        }
        dim3 grid(N_DIM / BN, M_DIM / BM);   // (8, 64)
        gemm_tf32_mma<<<grid, 512, SMEM_TOTAL>>>(gx, gwt, out);
    }
}

// round 11
// speedup vs baseline: 1.3372x; 1.0681x over previous
#include <cuda_runtime.h>
#include <cstdint>

// ============================================================================
// LoRA layer as one tf32 GEMM on the mma.sync (HMMA) path (ptxas targets
// sm_103 plain — no tcgen05 available).
//   out[8192,2048] = x[8192,2048] @ (W + A@B)[2048,2048]
//   1) convert_x:   x fp32 -> tf32(RNA) bits               (g_x, [M,K])
//   2) build_weffT: (W + A@B)^T -> tf32(RNA) bits          (g_WT, [N,K])
//   3) gemm: 128x128 CTA tile, BK=32, 256 thr (8 warps, 64x32 warp tile),
//      3-stage cp.async (96 KB -> 2 CTAs/SM), ldmatrix + mma.m16n8k8.tf32
// Round-10 change vs best (R7): same warp microkernel, but CTA tile 128x256 ->
// 128x128 with 3 stages so TWO CTAs fit per SM. The per-k-iter __syncthreads
// phase-lock of one CTA now overlaps the other CTA's MMA phase (R7 measured
// ~60% HMMA utilization with 1 CTA/SM).
// ============================================================================

#define M_DIM 8192
#define N_DIM 2048
#define K_DIM 2048

#define BM 128
#define BN 128
#define BK 32                      // tf32 elems (128 bytes) per row per stage
#define STAGES 3
#define KITERS (K_DIM / BK)        // 64

#define A_STAGE_BYTES (BM * 128)   // 16 KB
#define B_STAGE_BYTES (BN * 128)   // 16 KB
#define STAGE_BYTES (A_STAGE_BYTES + B_STAGE_BYTES)   // 32 KB
#define SMEM_TOTAL (STAGES * STAGE_BYTES)             // 96 KB -> 2 CTAs/SM

__device__ uint32_t g_x[(size_t)M_DIM * K_DIM];    // x as tf32 bits, [M,K]
__device__ uint32_t g_WT[(size_t)N_DIM * K_DIM];   // (W+AB)^T tf32 bits, [N,K]

// ---------------------------------------------------------------------------
// helpers
// ---------------------------------------------------------------------------
__device__ __forceinline__ uint32_t smem_u32(const void* p) {
    uint32_t a;
    asm("{ .reg .u64 t; cvta.to.shared.u64 t, %1; cvt.u32.u64 %0, t; }"
        : "=r"(a) : "l"(p));
    return a;
}
__device__ __forceinline__ uint32_t f2tf32(float f) {
    uint32_t r;
    asm("cvt.rna.tf32.f32 %0, %1;" : "=r"(r) : "f"(f));
    return r;
}
__device__ __forceinline__ void cp_async16(uint32_t s, const void* g) {
    asm volatile("cp.async.cg.shared.global [%0], [%1], 16;"
                 :: "r"(s), "l"(g) : "memory");
}
__device__ __forceinline__ void cp_commit() {
    asm volatile("cp.async.commit_group;" ::: "memory");
}
template <int N> __device__ __forceinline__ void cp_wait() {
    asm volatile("cp.async.wait_group %0;" :: "n"(N) : "memory");
}
__device__ __forceinline__ void ldsm_x4(uint32_t* r, uint32_t addr) {
    asm volatile("ldmatrix.sync.aligned.m8n8.x4.shared.b16 {%0,%1,%2,%3}, [%4];"
                 : "=r"(r[0]), "=r"(r[1]), "=r"(r[2]), "=r"(r[3]) : "r"(addr));
}
__device__ __forceinline__ void ldsm_x2(uint32_t* r, uint32_t addr) {
    asm volatile("ldmatrix.sync.aligned.m8n8.x2.shared.b16 {%0,%1}, [%2];"
                 : "=r"(r[0]), "=r"(r[1]) : "r"(addr));
}
__device__ __forceinline__ void mma_tf32(float* c, const uint32_t* a, const uint32_t* b) {
    asm volatile(
        "mma.sync.aligned.m16n8k8.row.col.f32.tf32.tf32.f32 "
        "{%0,%1,%2,%3}, {%4,%5,%6,%7}, {%8,%9}, {%0,%1,%2,%3};"
        : "+f"(c[0]), "+f"(c[1]), "+f"(c[2]), "+f"(c[3])
        : "r"(a[0]), "r"(a[1]), "r"(a[2]), "r"(a[3]), "r"(b[0]), "r"(b[1]));
}

// ---------------------------------------------------------------------------
// Kernel 1: x fp32 -> tf32(RNA) bits
// ---------------------------------------------------------------------------
__global__ void convert_x_kernel(const float4* __restrict__ x, uint4* __restrict__ gx) {
    int idx = blockIdx.x * blockDim.x + threadIdx.x;
    float4 v = x[idx];
    uint4 o;
    o.x = f2tf32(v.x); o.y = f2tf32(v.y); o.z = f2tf32(v.z); o.w = f2tf32(v.w);
    gx[idx] = o;
}

// ---------------------------------------------------------------------------
// Kernel 2: W_eff^T: out[n*K + c] = tf32( W[c*N + n] + sum_r A[c,r]*B[r,n] )
// ---------------------------------------------------------------------------
__global__ void build_weffT_kernel(const float* __restrict__ W,
                                   const float* __restrict__ A,
                                   const float* __restrict__ Bk,
                                   uint32_t* __restrict__ out) {
    __shared__ float t[32][33];
    int ci = blockIdx.y * 32;
    int ni = blockIdx.x * 32;
    #pragma unroll
    for (int i = 0; i < 4; i++) {
        int c = ci + threadIdx.y + i * 8;
        int n = ni + threadIdx.x;
        float w = W[(size_t)c * N_DIM + n];
        float a0 = A[c * 4 + 0], a1 = A[c * 4 + 1], a2 = A[c * 4 + 2], a3 = A[c * 4 + 3];
        w += a0 * Bk[n] + a1 * Bk[N_DIM + n] + a2 * Bk[2 * N_DIM + n] + a3 * Bk[3 * N_DIM + n];
        t[threadIdx.y + i * 8][threadIdx.x] = w;
    }
    __syncthreads();
    #pragma unroll
    for (int i = 0; i < 4; i++) {
        int n = ni + threadIdx.y + i * 8;
        int c = ci + threadIdx.x;
        out[(size_t)n * K_DIM + c] = f2tf32(t[threadIdx.x][threadIdx.y + i * 8]);
    }
}

// ---------------------------------------------------------------------------
// Kernel 3: tf32 mma.sync GEMM, 128x128 per CTA, 256 threads
//   warp grid 2(M) x 4(N); warp tile 64x32: 4 m-tiles(16) x 4 n-tiles(8)
// smem row = 32 tf32 = 128B = 8 chunks of 16B, chunk swizzle c ^= (row & 7)
// ---------------------------------------------------------------------------
__global__ __launch_bounds__(256, 2)
void gemm_tf32_mma(const uint32_t* __restrict__ gA,   // [M,K]
                   const uint32_t* __restrict__ gB,   // [N,K]
                   float* __restrict__ C) {
    extern __shared__ char smem[];
    const uint32_t sbase = smem_u32(smem);

    const int tid  = threadIdx.x;
    const int wid  = tid >> 5;
    const int lane = tid & 31;
    const int wm = wid & 1;        // 0..1  (M)
    const int wn = wid >> 1;       // 0..3  (N)

    const int bm = blockIdx.y;     // 0..63
    const int bn = blockIdx.x;     // 0..15

    // ---- cp.async mappings --------------------------------------------------
    // A: 128 rows x 8 chunks = 1024 chunks -> 4 per thread (2 threads/row)
    const int arow = tid >> 1;                 // 0..127
    const int ac0  = (tid & 1) * 4;            // chunks ac0..ac0+3
    // B: identical shape
    const int brow = arow;
    const int bc0  = ac0;

    const uint32_t* gAp = gA + (size_t)(bm * BM + arow) * K_DIM;
    const uint32_t* gBp = gB + (size_t)(bn * BN + brow) * K_DIM;

    auto load_stage = [&](int s) {
        uint32_t st = sbase + (s % STAGES) * STAGE_BYTES;
        uint32_t sa = st + arow * 128;
        uint32_t sb = st + A_STAGE_BYTES + brow * 128;
        const uint32_t* ga = gAp + s * BK;
        const uint32_t* gb = gBp + s * BK;
        #pragma unroll
        for (int j = 0; j < 4; j++) {
            int c = ac0 + j;
            cp_async16(sa + ((c ^ (arow & 7)) << 4), ga + c * 4);
        }
        #pragma unroll
        for (int j = 0; j < 4; j++) {
            int c = bc0 + j;
            cp_async16(sb + ((c ^ (brow & 7)) << 4), gb + c * 4);
        }
    };

    // ---- ldmatrix address bases (identical to R7 microkernel) --------------
    const int a_r = wm * 64 + (lane & 15);
    const int a_h = lane >> 4;            // 0/1
    const int r7  = lane & 7;
    const int b_r = wn * 32 + (lane & 7);
    const int b_h = (lane >> 3) & 1;

    float acc[4][4][4];
    #pragma unroll
    for (int i = 0; i < 4; i++)
        #pragma unroll
        for (int j = 0; j < 4; j++)
            #pragma unroll
            for (int q = 0; q < 4; q++)
                acc[i][j][q] = 0.0f;

    // ---- prologue ----------------------------------------------------------
    #pragma unroll
    for (int s = 0; s < STAGES - 1; s++) { load_stage(s); cp_commit(); }

    // ---- main loop ---------------------------------------------------------
    for (int k = 0; k < KITERS; k++) {
        cp_wait<STAGES - 2>();
        __syncthreads();

        uint32_t st = sbase + (k % STAGES) * STAGE_BYTES;
        uint32_t sa = st + a_r * 128;
        uint32_t sb = st + A_STAGE_BYTES + b_r * 128;

        #pragma unroll
        for (int ks = 0; ks < 4; ks++) {
            uint32_t afr[4][4];
            uint32_t bfr[4][2];
            const int ca = ((2 * ks + a_h) ^ r7) << 4;
            const int cb = ((2 * ks + b_h) ^ r7) << 4;
            #pragma unroll
            for (int mt = 0; mt < 4; mt++)
                ldsm_x4(afr[mt], sa + mt * (16 * 128) + ca);
            #pragma unroll
            for (int nt = 0; nt < 4; nt++)
                ldsm_x2(bfr[nt], sb + nt * (8 * 128) + cb);
            #pragma unroll
            for (int mt = 0; mt < 4; mt++)
                #pragma unroll
                for (int nt = 0; nt < 4; nt++)
                    mma_tf32(acc[mt][nt], afr[mt], bfr[nt]);
        }

        if (k + STAGES - 1 < KITERS) load_stage(k + STAGES - 1);
        cp_commit();
    }

    // ---- epilogue ----------------------------------------------------------
    const int er = lane >> 2;
    const int ec = (lane & 3) * 2;
    #pragma unroll
    for (int mt = 0; mt < 4; mt++) {
        int m0 = bm * BM + wm * 64 + mt * 16 + er;
        #pragma unroll
        for (int nt = 0; nt < 4; nt++) {
            int n0 = bn * BN + wn * 32 + nt * 8 + ec;
            *(float2*)(C + (size_t)m0 * N_DIM + n0) =
                make_float2(acc[mt][nt][0], acc[mt][nt][1]);
            *(float2*)(C + (size_t)(m0 + 8) * N_DIM + n0) =
                make_float2(acc[mt][nt][2], acc[mt][nt][3]);
        }
    }
}

// ---------------------------------------------------------------------------
// Launch
// ---------------------------------------------------------------------------
extern "C" void kernel_launch(void* const* d_in, const int* in_sizes, int n_in,
                              void* d_out, int out_size) {
    const float* x  = (const float*)d_in[0];   // [8192, 2048]
    const float* W  = (const float*)d_in[1];   // [2048, 2048]
    const float* A  = (const float*)d_in[2];   // [2048, 4]
    const float* Bk = (const float*)d_in[3];   // [4, 2048]
    float* out = (float*)d_out;

    uint32_t *gx, *gwt;
    cudaGetSymbolAddress((void**)&gx, g_x);
    cudaGetSymbolAddress((void**)&gwt, g_WT);

    // 1) x -> tf32 bits
    {
        int total4 = (M_DIM * K_DIM) / 4;
        convert_x_kernel<<<total4 / 256, 256>>>((const float4*)x, (uint4*)gx);
    }
    // 2) W_eff^T -> tf32 bits
    {
        dim3 grid(N_DIM / 32, K_DIM / 32);
        dim3 block(32, 8);
        build_weffT_kernel<<<grid, block>>>(W, A, Bk, gwt);
    }
    // 3) GEMM
    {
        static bool attr_set = false;
        if (!attr_set) {
            cudaFuncSetAttribute(gemm_tf32_mma,
                                 cudaFuncAttributeMaxDynamicSharedMemorySize, SMEM_TOTAL);
            attr_set = true;
        }
        dim3 grid(N_DIM / BN, M_DIM / BM);   // (16, 64)
        gemm_tf32_mma<<<grid, 256, SMEM_TOTAL>>>(gx, gwt, out);
    }
}

// round 12
// speedup vs baseline: 2.5993x; 1.9438x over previous
#include <cuda_runtime.h>
#include <cuda_fp16.h>
#include <cstdint>

// ============================================================================
// LoRA layer as one fp16-input / fp32-accumulate GEMM on mma.sync (ptxas
// targets sm_103 plain — no tcgen05 available).
//   out[8192,2048] = x[8192,2048] @ (W + A@B)[2048,2048]
// fp16 has the SAME 10-bit mantissa as tf32 -> same rel_err (~2.9e-4), but
// m16n8k16 does 2x MACs/instr and fragments are half the bytes: halves both
// the HMMA instruction count and the smem/ldsm + L2 traffic vs the tf32 path.
//   1) convert_x:   x fp32 -> fp16                         (g_x, [M,K])
//   2) build_weffT: (W + A@B)^T -> fp16                    (g_WT, [N,K])
//   3) gemm: 128x256 CTA tile, BK=64 (128B rows), 512 thr (16 warps,
//      64x32 warp tile), 4-stage cp.async, ldmatrix + mma.m16n8k16.f16
// Structure is identical to the best tf32 kernel (R7); only the element type
// and K-step bookkeeping change.
// ============================================================================

#define M_DIM 8192
#define N_DIM 2048
#define K_DIM 2048

#define BM 128
#define BN 256
#define BK 64                      // fp16 elems (128 bytes) per row per stage
#define STAGES 4
#define KITERS (K_DIM / BK)        // 32

#define A_STAGE_BYTES (BM * 128)   // 16 KB
#define B_STAGE_BYTES (BN * 128)   // 32 KB
#define STAGE_BYTES (A_STAGE_BYTES + B_STAGE_BYTES)   // 48 KB
#define SMEM_TOTAL (STAGES * STAGE_BYTES)             // 192 KB

__device__ __half g_x[(size_t)M_DIM * K_DIM];    // x as fp16, [M,K]
__device__ __half g_WT[(size_t)N_DIM * K_DIM];   // (W+AB)^T fp16, [N,K]

// ---------------------------------------------------------------------------
// helpers
// ---------------------------------------------------------------------------
__device__ __forceinline__ uint32_t smem_u32(const void* p) {
    uint32_t a;
    asm("{ .reg .u64 t; cvta.to.shared.u64 t, %1; cvt.u32.u64 %0, t; }"
        : "=r"(a) : "l"(p));
    return a;
}
__device__ __forceinline__ void cp_async16(uint32_t s, const void* g) {
    asm volatile("cp.async.cg.shared.global [%0], [%1], 16;"
                 :: "r"(s), "l"(g) : "memory");
}
__device__ __forceinline__ void cp_commit() {
    asm volatile("cp.async.commit_group;" ::: "memory");
}
template <int N> __device__ __forceinline__ void cp_wait() {
    asm volatile("cp.async.wait_group %0;" :: "n"(N) : "memory");
}
__device__ __forceinline__ void ldsm_x4(uint32_t* r, uint32_t addr) {
    asm volatile("ldmatrix.sync.aligned.m8n8.x4.shared.b16 {%0,%1,%2,%3}, [%4];"
                 : "=r"(r[0]), "=r"(r[1]), "=r"(r[2]), "=r"(r[3]) : "r"(addr));
}
__device__ __forceinline__ void ldsm_x2(uint32_t* r, uint32_t addr) {
    asm volatile("ldmatrix.sync.aligned.m8n8.x2.shared.b16 {%0,%1}, [%2];"
                 : "=r"(r[0]), "=r"(r[1]) : "r"(addr));
}
__device__ __forceinline__ void mma_f16(float* c, const uint32_t* a, const uint32_t* b) {
    asm volatile(
        "mma.sync.aligned.m16n8k16.row.col.f32.f16.f16.f32 "
        "{%0,%1,%2,%3}, {%4,%5,%6,%7}, {%8,%9}, {%0,%1,%2,%3};"
        : "+f"(c[0]), "+f"(c[1]), "+f"(c[2]), "+f"(c[3])
        : "r"(a[0]), "r"(a[1]), "r"(a[2]), "r"(a[3]), "r"(b[0]), "r"(b[1]));
}

// ---------------------------------------------------------------------------
// Kernel 1: x fp32 -> fp16   (reads float4, writes half2 x2 = 16B -> 8B)
// ---------------------------------------------------------------------------
__global__ void convert_x_kernel(const float4* __restrict__ x, __half2* __restrict__ gx) {
    int idx = blockIdx.x * blockDim.x + threadIdx.x;   // float4 index
    float4 v = x[idx];
    gx[idx * 2 + 0] = __floats2half2_rn(v.x, v.y);
    gx[idx * 2 + 1] = __floats2half2_rn(v.z, v.w);
}

// ---------------------------------------------------------------------------
// Kernel 2: W_eff^T: out[n*K + c] = fp16( W[c*N + n] + sum_r A[c,r]*B[r,n] )
// ---------------------------------------------------------------------------
__global__ void build_weffT_kernel(const float* __restrict__ W,
                                   const float* __restrict__ A,
                                   const float* __restrict__ Bk,
                                   __half* __restrict__ out) {
    __shared__ float t[32][33];
    int ci = blockIdx.y * 32;
    int ni = blockIdx.x * 32;
    #pragma unroll
    for (int i = 0; i < 4; i++) {
        int c = ci + threadIdx.y + i * 8;
        int n = ni + threadIdx.x;
        float w = W[(size_t)c * N_DIM + n];
        float a0 = A[c * 4 + 0], a1 = A[c * 4 + 1], a2 = A[c * 4 + 2], a3 = A[c * 4 + 3];
        w += a0 * Bk[n] + a1 * Bk[N_DIM + n] + a2 * Bk[2 * N_DIM + n] + a3 * Bk[3 * N_DIM + n];
        t[threadIdx.y + i * 8][threadIdx.x] = w;
    }
    __syncthreads();
    #pragma unroll
    for (int i = 0; i < 4; i++) {
        int n = ni + threadIdx.y + i * 8;
        int c = ci + threadIdx.x;
        out[(size_t)n * K_DIM + c] = __float2half_rn(t[threadIdx.x][threadIdx.y + i * 8]);
    }
}

// ---------------------------------------------------------------------------
// Kernel 3: fp16 mma.sync GEMM, 128x256 per CTA, 512 threads
//   warp grid 2(M) x 8(N); warp tile 64x32: 4 m-tiles(16) x 4 n-tiles(8)
// smem row = 64 fp16 = 128B = 8 chunks of 16B, chunk swizzle c ^= (row & 7)
// Each k-iter (BK=64) = 4 k16 MMA steps.
// ---------------------------------------------------------------------------
__global__ __launch_bounds__(512, 1)
void gemm_f16_mma(const __half* __restrict__ gA,   // [M,K]
                  const __half* __restrict__ gB,   // [N,K]
                  float* __restrict__ C) {
    extern __shared__ char smem[];
    const uint32_t sbase = smem_u32(smem);

    const int tid  = threadIdx.x;
    const int wid  = tid >> 5;
    const int lane = tid & 31;
    const int wm = wid & 1;        // 0..1  (M)
    const int wn = wid >> 1;       // 0..7  (N)

    const int bm = blockIdx.y;     // 0..63
    const int bn = blockIdx.x;     // 0..7

    // ---- cp.async mappings --------------------------------------------------
    // A: 128 rows x 8 chunks = 1024 chunks -> 2 per thread
    const int arow = tid >> 2;                 // 0..127
    const int ac0  = (tid & 3) * 2;            // chunks ac0, ac0+1
    // B: 256 rows x 8 chunks = 2048 chunks -> 4 per thread
    const int brow = tid >> 1;                 // 0..255
    const int bc0  = (tid & 1) * 4;            // chunks bc0..bc0+3

    const char* gAp = (const char*)(gA + (size_t)(bm * BM + arow) * K_DIM);
    const char* gBp = (const char*)(gB + (size_t)(bn * BN + brow) * K_DIM);

    auto load_stage = [&](int s) {
        uint32_t st = sbase + (s % STAGES) * STAGE_BYTES;
        uint32_t sa = st + arow * 128;
        uint32_t sb = st + A_STAGE_BYTES + brow * 128;
        const char* ga = gAp + (size_t)s * 128;   // BK=64 fp16 = 128B along K
        const char* gb = gBp + (size_t)s * 128;
        #pragma unroll
        for (int j = 0; j < 2; j++) {
            int c = ac0 + j;
            cp_async16(sa + ((c ^ (arow & 7)) << 4), ga + c * 16);
        }
        #pragma unroll
        for (int j = 0; j < 4; j++) {
            int c = bc0 + j;
            cp_async16(sb + ((c ^ (brow & 7)) << 4), gb + c * 16);
        }
    };

    // ---- ldmatrix address bases --------------------------------------------
    // A (m16k16, ldsm_x4): row = wm*64 + mt*16 + (lane&15); k-half (16B) = lane>>4
    // B (n8k16, ldsm_x2):  row = wn*32 + nt*8 + (lane&7);  k-half = (lane>>3)&1
    // chunk index within 128B row = 2*ks + half; swizzle ^ (row&7)
    const int a_r = wm * 64 + (lane & 15);
    const int a_h = lane >> 4;            // 0/1
    const int r7  = lane & 7;
    const int b_r = wn * 32 + (lane & 7);
    const int b_h = (lane >> 3) & 1;

    float acc[4][4][4];
    #pragma unroll
    for (int i = 0; i < 4; i++)
        #pragma unroll
        for (int j = 0; j < 4; j++)
            #pragma unroll
            for (int q = 0; q < 4; q++)
                acc[i][j][q] = 0.0f;

    // ---- prologue ----------------------------------------------------------
    #pragma unroll
    for (int s = 0; s < STAGES - 1; s++) { load_stage(s); cp_commit(); }

    // ---- main loop ---------------------------------------------------------
    for (int k = 0; k < KITERS; k++) {
        cp_wait<STAGES - 2>();
        __syncthreads();

        uint32_t st = sbase + (k % STAGES) * STAGE_BYTES;
        uint32_t sa = st + a_r * 128;
        uint32_t sb = st + A_STAGE_BYTES + b_r * 128;

        #pragma unroll
        for (int ks = 0; ks < 4; ks++) {
            uint32_t afr[4][4];
            uint32_t bfr[4][2];
            const int ca = ((2 * ks + a_h) ^ r7) << 4;
            const int cb = ((2 * ks + b_h) ^ r7) << 4;
            #pragma unroll
            for (int mt = 0; mt < 4; mt++)
                ldsm_x4(afr[mt], sa + mt * (16 * 128) + ca);
            #pragma unroll
            for (int nt = 0; nt < 4; nt++)
                ldsm_x2(bfr[nt], sb + nt * (8 * 128) + cb);
            #pragma unroll
            for (int mt = 0; mt < 4; mt++)
                #pragma unroll
                for (int nt = 0; nt < 4; nt++)
                    mma_f16(acc[mt][nt], afr[mt], bfr[nt]);
        }

        if (k + STAGES - 1 < KITERS) load_stage(k + STAGES - 1);
        cp_commit();
    }

    // ---- epilogue ----------------------------------------------------------
    const int er = lane >> 2;
    const int ec = (lane & 3) * 2;
    #pragma unroll
    for (int mt = 0; mt < 4; mt++) {
        int m0 = bm * BM + wm * 64 + mt * 16 + er;
        #pragma unroll
        for (int nt = 0; nt < 4; nt++) {
            int n0 = bn * BN + wn * 32 + nt * 8 + ec;
            *(float2*)(C + (size_t)m0 * N_DIM + n0) =
                make_float2(acc[mt][nt][0], acc[mt][nt][1]);
            *(float2*)(C + (size_t)(m0 + 8) * N_DIM + n0) =
                make_float2(acc[mt][nt][2], acc[mt][nt][3]);
        }
    }
}

// ---------------------------------------------------------------------------
// Launch
// ---------------------------------------------------------------------------
extern "C" void kernel_launch(void* const* d_in, const int* in_sizes, int n_in,
                              void* d_out, int out_size) {
    const float* x  = (const float*)d_in[0];   // [8192, 2048]
    const float* W  = (const float*)d_in[1];   // [2048, 2048]
    const float* A  = (const float*)d_in[2];   // [2048, 4]
    const float* Bk = (const float*)d_in[3];   // [4, 2048]
    float* out = (float*)d_out;

    __half *gx, *gwt;
    cudaGetSymbolAddress((void**)&gx, g_x);
    cudaGetSymbolAddress((void**)&gwt, g_WT);

    // 1) x -> fp16
    {
        int total4 = (M_DIM * K_DIM) / 4;
        convert_x_kernel<<<total4 / 256, 256>>>((const float4*)x, (__half2*)gx);
    }
    // 2) W_eff^T -> fp16
    {
        dim3 grid(N_DIM / 32, K_DIM / 32);
        dim3 block(32, 8);
        build_weffT_kernel<<<grid, block>>>(W, A, Bk, gwt);
    }
    // 3) GEMM
    {
        static bool attr_set = false;
        if (!attr_set) {
            cudaFuncSetAttribute(gemm_f16_mma,
                                 cudaFuncAttributeMaxDynamicSharedMemorySize, SMEM_TOTAL);
            attr_set = true;
        }
        dim3 grid(N_DIM / BN, M_DIM / BM);   // (8, 64)
        gemm_f16_mma<<<grid, 512, SMEM_TOTAL>>>(gx, gwt, out);
    }
}